// round 1
// baseline (speedup 1.0000x reference)
#include <cuda_runtime.h>
#include <cstdint>

// Problem constants
#define BATCH   16
#define HW      (1024 * 1024)
#define HW4     (HW / 4)
#define GRIDX   74
#define NTHREADS 256
#define NQ      7   // focal, ce, p, p*t, t, bin, bin*t
#define SMOOTH  1e-6f

// Per-block partials: [BATCH][GRIDX][8] (padded to 8 floats for alignment)
__device__ float g_part[BATCH * GRIDX * 8];

struct Acc {
    float focal, ce, p, pt, t, bin, bint;
};

__device__ __forceinline__ void accum_elem(Acc& a, float x, float t) {
    float ax  = fabsf(x);
    float e   = __expf(-ax);                    // exp(-|x|), in (0,1]
    float inv = __fdividef(1.0f, 1.0f + e);     // 1/(1+e)
    bool  pos = (x > 0.0f);
    float p   = pos ? inv : e * inv;            // sigmoid(x)
    // stable softplus: max(x,0) + log(1+exp(-|x|))
    float ce  = fmaxf(x, 0.0f) + __logf(1.0f + e) - x * t;
    // t in {0,1}: 1 - p_t = t ? (1-p) : p ; alpha_t = t ? 0.25 : 0.75
    float omp   = (t > 0.5f) ? (1.0f - p) : p;
    float alpha = 0.75f - 0.5f * t;
    a.focal += alpha * ce * omp * omp;
    a.ce    += ce;
    a.p     += p;
    a.pt    += p * t;
    a.t     += t;
    float binf = pos ? 1.0f : 0.0f;
    a.bin  += binf;
    a.bint += binf * t;
}

__device__ __forceinline__ float warp_sum(float v) {
    #pragma unroll
    for (int off = 16; off > 0; off >>= 1)
        v += __shfl_xor_sync(0xFFFFFFFFu, v, off);
    return v;
}

__global__ __launch_bounds__(NTHREADS)
void loss_main_kernel(const float4* __restrict__ pred,
                      const float4* __restrict__ gt) {
    const int img = blockIdx.y;
    const float4* px = pred + (size_t)img * HW4;
    const float4* tx = gt   + (size_t)img * HW4;

    Acc a = {0.f, 0.f, 0.f, 0.f, 0.f, 0.f, 0.f};

    const int stride = gridDim.x * blockDim.x;
    for (int i = blockIdx.x * blockDim.x + threadIdx.x; i < HW4; i += stride) {
        float4 xv = __ldg(px + i);
        float4 tv = __ldg(tx + i);
        accum_elem(a, xv.x, tv.x);
        accum_elem(a, xv.y, tv.y);
        accum_elem(a, xv.z, tv.z);
        accum_elem(a, xv.w, tv.w);
    }

    // block reduction: warp shuffle then smem across warps
    float vals[NQ] = {a.focal, a.ce, a.p, a.pt, a.t, a.bin, a.bint};
    #pragma unroll
    for (int q = 0; q < NQ; q++) vals[q] = warp_sum(vals[q]);

    __shared__ float sm[NTHREADS / 32][NQ];
    const int lane = threadIdx.x & 31;
    const int warp = threadIdx.x >> 5;
    if (lane == 0) {
        #pragma unroll
        for (int q = 0; q < NQ; q++) sm[warp][q] = vals[q];
    }
    __syncthreads();

    if (warp == 0) {
        #pragma unroll
        for (int q = 0; q < NQ; q++) {
            float v = (lane < NTHREADS / 32) ? sm[lane][q] : 0.0f;
            v = warp_sum(v);
            if (lane == 0) vals[q] = v;
        }
        if (lane == 0) {
            float* dst = g_part + ((size_t)img * GRIDX + blockIdx.x) * 8;
            #pragma unroll
            for (int q = 0; q < NQ; q++) dst[q] = vals[q];
        }
    }
}

__global__ __launch_bounds__(512)
void loss_final_kernel(const float* __restrict__ pred_iou,
                       float* __restrict__ out) {
    const int w    = threadIdx.x >> 5;   // image index, 16 warps
    const int lane = threadIdx.x & 31;

    float s[NQ] = {0.f, 0.f, 0.f, 0.f, 0.f, 0.f, 0.f};
    for (int j = lane; j < GRIDX; j += 32) {
        const float* q = g_part + ((size_t)w * GRIDX + j) * 8;
        #pragma unroll
        for (int k = 0; k < NQ; k++) s[k] += q[k];
    }
    #pragma unroll
    for (int k = 0; k < NQ; k++) s[k] = warp_sum(s[k]);

    __shared__ float agg[BATCH][4];
    if (lane == 0) {
        // s: 0=focal 1=ce 2=p 3=pt 4=t 5=bin 6=bint
        float dice_term = (2.0f * s[3] + SMOOTH) / (s[2] + s[4] + SMOOTH);
        float inter = s[6];
        float uni   = s[5] + s[4] - s[6];
        float actual = (inter + SMOOTH) / (uni + SMOOTH);
        float d = pred_iou[w] - actual;
        agg[w][0] = s[0];          // focal sum
        agg[w][1] = s[1];          // ce sum
        agg[w][2] = dice_term;
        agg[w][3] = d * d;
    }
    __syncthreads();

    if (threadIdx.x == 0) {
        float fsum = 0.f, csum = 0.f, dsum = 0.f, isum = 0.f;
        #pragma unroll
        for (int b = 0; b < BATCH; b++) {
            fsum += agg[b][0];
            csum += agg[b][1];
            dsum += agg[b][2];
            isum += agg[b][3];
        }
        const float invN = 1.0f / (float)((long long)BATCH * HW);
        float focal    = fsum * invN;
        float dice     = 1.0f - dsum / (float)BATCH;
        // total = focal + dice + 0.5 * (2 * mean(ce)) = focal + dice + mean(ce)
        float boundary = csum * invN;
        float iou_loss = 0.1f * (isum / (float)BATCH);
        out[0] = focal + dice + boundary + iou_loss;
    }
}

extern "C" void kernel_launch(void* const* d_in, const int* in_sizes, int n_in,
                              void* d_out, int out_size) {
    const float4* pred = (const float4*)d_in[0];
    const float4* gt   = (const float4*)d_in[1];
    const float*  piou = (const float*)d_in[2];
    float* out = (float*)d_out;

    dim3 grid(GRIDX, BATCH);
    loss_main_kernel<<<grid, NTHREADS>>>(pred, gt);
    loss_final_kernel<<<1, 512>>>(piou, out);
}